// round 10
// baseline (speedup 1.0000x reference)
#include <cuda_runtime.h>
#include <stdint.h>

// reference(x) = (U*S)@Vh from SVD of x == exact SVD reconstruction == x.
// Kernel = pure D2D streaming copy of N*3*3 floats (75.5 MB R+W, HBM-bound,
// ~6.9 TB/s combined = ~86% of spec — at the roofline).
//
// R10: reduce cross-CTA L1tex-queue contention (B300 spread model:
// spr_max@occ8 monotone in MLP_p1 = consecutive front-batched LDG.128).
// Split the 8-deep load batch into two 4-deep ld/st half-batches:
// MLP_p1 8 -> 4, oe*MLP_p1 64 -> 32, shrinking the slowest-CTA tail that
// sets the single-wave kernel time. Per-warp MLP stays 4x32=128 loads in
// flight — far above the latency-hiding requirement.
//
// Falsified alternatives: .cs/.cg (11.07), v8 256-bit (12.29),
// v8+evict_last (11.26), driver memcpy (11.49), 32-bit idx (11.84).
// Bench noise is ~±1us (byte-exact R2 re-run: 11.01 vs 12.13).

#define CP_THREADS 256
#define CP_UNROLL  8
#define CP_HALF    4

__global__ void __launch_bounds__(CP_THREADS) copy_split_kernel(
    const float4* __restrict__ src, float4* __restrict__ dst, long long n4)
{
    long long base = (long long)blockIdx.x * (CP_THREADS * CP_UNROLL) + threadIdx.x;

    if (base + (long long)(CP_UNROLL - 1) * CP_THREADS < n4) {
        float4 v[CP_HALF];
        // half-batch 1: 4 loads in flight, then drain to stores
#pragma unroll
        for (int u = 0; u < CP_HALF; u++)
            v[u] = src[base + (long long)u * CP_THREADS];
#pragma unroll
        for (int u = 0; u < CP_HALF; u++)
            dst[base + (long long)u * CP_THREADS] = v[u];
        // half-batch 2
#pragma unroll
        for (int u = CP_HALF; u < CP_UNROLL; u++)
            v[u - CP_HALF] = src[base + (long long)u * CP_THREADS];
#pragma unroll
        for (int u = CP_HALF; u < CP_UNROLL; u++)
            dst[base + (long long)u * CP_THREADS] = v[u - CP_HALF];
    } else {
#pragma unroll
        for (int u = 0; u < CP_UNROLL; u++) {
            long long i = base + (long long)u * CP_THREADS;
            if (i < n4) dst[i] = src[i];
        }
    }
}

__global__ void __launch_bounds__(256) copy_f_tail_kernel(
    const float* __restrict__ src, float* __restrict__ dst,
    long long start, long long n)
{
    long long i = start + (long long)blockIdx.x * blockDim.x + threadIdx.x;
    if (i < n) dst[i] = src[i];
}

extern "C" void kernel_launch(void* const* d_in, const int* in_sizes, int n_in,
                              void* d_out, int out_size) {
    const float* x = (const float*)d_in[0];
    float* out = (float*)d_out;
    long long n = (long long)in_sizes[0];   // total float elements (N*3*3)

    long long n4 = n / 4;
    if (n4 > 0) {
        long long per_block = (long long)CP_THREADS * CP_UNROLL;
        int blocks = (int)((n4 + per_block - 1) / per_block);
        copy_split_kernel<<<blocks, CP_THREADS>>>((const float4*)x, (float4*)out, n4);
    }
    long long tail_start = n4 * 4;
    if (n - tail_start > 0) {
        copy_f_tail_kernel<<<1, 256>>>(x, out, tail_start, n);
    }
}

// round 11
// speedup vs baseline: 1.0706x; 1.0706x over previous
#include <cuda_runtime.h>
#include <stdint.h>

// reference(x) = (U*S)@Vh from SVD of x == exact SVD reconstruction == x.
// Kernel = pure D2D streaming copy of N*3*3 floats (75.5 MB R+W, HBM-bound).
//
// FINAL — champion configuration (best measured sample: 11.008us,
// ~6.9 TB/s combined = 86% of 8 TB/s HBM spec). Ten rounds of alternatives
// all falsified or within the bench's ±1us noise band:
//   .cs/.cg policies 11.07 | v8 256-bit 12.29 | v8+evict_last 11.26
//   driver memcpy 11.49 | 32-bit idx 11.84 | split ld/st batches 12.13
//   byte-exact re-run of this file: 11.01 / 12.13 (noise bound).
// An identity copy has no traffic/fusion/compute lever; this is the
// HBM read+write roofline.
//
// Strategy: 8 independent float4 loads per thread (MLP=8, 128B/thread),
// block-strided for perfect coalescing, exact-fit single-wave grid
// (1152 blocks = ~8 CTAs x 148 SMs) so the hot path has no bounds checks
// and no loop-carried arithmetic.

#define CP_THREADS 256
#define CP_UNROLL  8

__global__ void __launch_bounds__(CP_THREADS) copy_unroll_kernel(
    const float4* __restrict__ src, float4* __restrict__ dst, long long n4)
{
    long long base = (long long)blockIdx.x * (CP_THREADS * CP_UNROLL) + threadIdx.x;

    if (base + (long long)(CP_UNROLL - 1) * CP_THREADS < n4) {
        float4 v[CP_UNROLL];
#pragma unroll
        for (int u = 0; u < CP_UNROLL; u++)
            v[u] = src[base + (long long)u * CP_THREADS];
#pragma unroll
        for (int u = 0; u < CP_UNROLL; u++)
            dst[base + (long long)u * CP_THREADS] = v[u];
    } else {
#pragma unroll
        for (int u = 0; u < CP_UNROLL; u++) {
            long long i = base + (long long)u * CP_THREADS;
            if (i < n4) dst[i] = src[i];
        }
    }
}

__global__ void __launch_bounds__(256) copy_f_tail_kernel(
    const float* __restrict__ src, float* __restrict__ dst,
    long long start, long long n)
{
    long long i = start + (long long)blockIdx.x * blockDim.x + threadIdx.x;
    if (i < n) dst[i] = src[i];
}

extern "C" void kernel_launch(void* const* d_in, const int* in_sizes, int n_in,
                              void* d_out, int out_size) {
    const float* x = (const float*)d_in[0];
    float* out = (float*)d_out;
    long long n = (long long)in_sizes[0];   // total float elements (N*3*3)

    long long n4 = n / 4;
    if (n4 > 0) {
        long long per_block = (long long)CP_THREADS * CP_UNROLL;
        int blocks = (int)((n4 + per_block - 1) / per_block);
        copy_unroll_kernel<<<blocks, CP_THREADS>>>((const float4*)x, (float4*)out, n4);
    }
    long long tail_start = n4 * 4;
    if (n - tail_start > 0) {
        copy_f_tail_kernel<<<1, 256>>>(x, out, tail_start, n);
    }
}